// round 3
// baseline (speedup 1.0000x reference)
#include <cuda_runtime.h>

// Depthwise causal conv1d, channel-last. x:(B,L,D) fp32; w:(K=4,1,D); b:(D,).
// y[b,l,d] = bias[d] + sum_k x[b,l+k-3,d]*w[k,d]
//
// R3: one-wave strip decomposition. Exactly NSTRIPS x ngroups x B = 592 blocks
// (148 SMs x 4 resident) -> zero wave-quantization tail. Each block owns a
// contiguous l-strip (~55 rows); sliding register history -> halo = 3/55 = 5.4%.
// Inner loop unrolled x4 with batched independent loads (MLP=4/thread).

#define THREADS 256

__global__ void __launch_bounds__(THREADS, 4) dwconv_kernel(
    const float4* __restrict__ x,
    const float4* __restrict__ w,
    const float4* __restrict__ bias,
    float4* __restrict__ y,
    int L, int D4, int nstrips)
{
    const int d4 = blockIdx.y * THREADS + threadIdx.x;  // channel group (fixed)
    const int b  = blockIdx.z;
    const int s  = blockIdx.x;

    // strip bounds: balanced partition of [0, L)
    const int l_start = (int)(((long)s * L) / nstrips);
    const int l_end   = (int)(((long)(s + 1) * L) / nstrips);

    // K=4 weights + bias in registers
    const float4 w0 = w[0 * D4 + d4];
    const float4 w1 = w[1 * D4 + d4];
    const float4 w2 = w[2 * D4 + d4];
    const float4 w3 = w[3 * D4 + d4];
    const float4 bb = bias[d4];
    const float4 z4 = make_float4(0.f, 0.f, 0.f, 0.f);

    const int base = (b * L) * D4 + d4;   // (b, l=0, d4); fits 32-bit

    // history window x[l_start-3 .. l_start-1], zero-padded at sequence start
    float4 h0, h1, h2;
    if (l_start >= 3) {
        h0 = x[base + (l_start - 3) * D4];
        h1 = x[base + (l_start - 2) * D4];
        h2 = x[base + (l_start - 1) * D4];
    } else {
        h0 = z4; h1 = z4; h2 = z4;   // l_start == 0
    }

    int l = l_start;
    int idx = base + l * D4;

    // main loop: 4 rows per iteration, loads batched up front for MLP
    for (; l + 4 <= l_end; l += 4, idx += 4 * D4) {
        const float4 x0 = x[idx];
        const float4 x1 = x[idx + 1 * D4];
        const float4 x2 = x[idx + 2 * D4];
        const float4 x3 = x[idx + 3 * D4];

        float4 o0, o1, o2, o3;
        o0.x = fmaf(w3.x, x0.x, fmaf(w2.x, h2.x, fmaf(w1.x, h1.x, fmaf(w0.x, h0.x, bb.x))));
        o0.y = fmaf(w3.y, x0.y, fmaf(w2.y, h2.y, fmaf(w1.y, h1.y, fmaf(w0.y, h0.y, bb.y))));
        o0.z = fmaf(w3.z, x0.z, fmaf(w2.z, h2.z, fmaf(w1.z, h1.z, fmaf(w0.z, h0.z, bb.z))));
        o0.w = fmaf(w3.w, x0.w, fmaf(w2.w, h2.w, fmaf(w1.w, h1.w, fmaf(w0.w, h0.w, bb.w))));

        o1.x = fmaf(w3.x, x1.x, fmaf(w2.x, x0.x, fmaf(w1.x, h2.x, fmaf(w0.x, h1.x, bb.x))));
        o1.y = fmaf(w3.y, x1.y, fmaf(w2.y, x0.y, fmaf(w1.y, h2.y, fmaf(w0.y, h1.y, bb.y))));
        o1.z = fmaf(w3.z, x1.z, fmaf(w2.z, x0.z, fmaf(w1.z, h2.z, fmaf(w0.z, h1.z, bb.z))));
        o1.w = fmaf(w3.w, x1.w, fmaf(w2.w, x0.w, fmaf(w1.w, h2.w, fmaf(w0.w, h1.w, bb.w))));

        o2.x = fmaf(w3.x, x2.x, fmaf(w2.x, x1.x, fmaf(w1.x, x0.x, fmaf(w0.x, h2.x, bb.x))));
        o2.y = fmaf(w3.y, x2.y, fmaf(w2.y, x1.y, fmaf(w1.y, x0.y, fmaf(w0.y, h2.y, bb.y))));
        o2.z = fmaf(w3.z, x2.z, fmaf(w2.z, x1.z, fmaf(w1.z, x0.z, fmaf(w0.z, h2.z, bb.z))));
        o2.w = fmaf(w3.w, x2.w, fmaf(w2.w, x1.w, fmaf(w1.w, x0.w, fmaf(w0.w, h2.w, bb.w))));

        o3.x = fmaf(w3.x, x3.x, fmaf(w2.x, x2.x, fmaf(w1.x, x1.x, fmaf(w0.x, x0.x, bb.x))));
        o3.y = fmaf(w3.y, x3.y, fmaf(w2.y, x2.y, fmaf(w1.y, x1.y, fmaf(w0.y, x0.y, bb.y))));
        o3.z = fmaf(w3.z, x3.z, fmaf(w2.z, x2.z, fmaf(w1.z, x1.z, fmaf(w0.z, x0.z, bb.z))));
        o3.w = fmaf(w3.w, x3.w, fmaf(w2.w, x2.w, fmaf(w1.w, x1.w, fmaf(w0.w, x0.w, bb.w))));

        y[idx]          = o0;
        y[idx + 1 * D4] = o1;
        y[idx + 2 * D4] = o2;
        y[idx + 3 * D4] = o3;

        h0 = x1; h1 = x2; h2 = x3;
    }

    // remainder rows
    for (; l < l_end; ++l, idx += D4) {
        const float4 xc = x[idx];
        float4 o;
        o.x = fmaf(w3.x, xc.x, fmaf(w2.x, h2.x, fmaf(w1.x, h1.x, fmaf(w0.x, h0.x, bb.x))));
        o.y = fmaf(w3.y, xc.y, fmaf(w2.y, h2.y, fmaf(w1.y, h1.y, fmaf(w0.y, h0.y, bb.y))));
        o.z = fmaf(w3.z, xc.z, fmaf(w2.z, h2.z, fmaf(w1.z, h1.z, fmaf(w0.z, h0.z, bb.z))));
        o.w = fmaf(w3.w, xc.w, fmaf(w2.w, h2.w, fmaf(w1.w, h1.w, fmaf(w0.w, h0.w, bb.w))));
        y[idx] = o;
        h0 = h1; h1 = h2; h2 = xc;
    }
}

extern "C" void kernel_launch(void* const* d_in, const int* in_sizes, int n_in,
                              void* d_out, int out_size)
{
    const float* x  = (const float*)d_in[0];
    const float* w  = (const float*)d_in[1];
    const float* bi = (const float*)d_in[2];
    float* y = (float*)d_out;

    const int D  = in_sizes[2];            // 2048
    const int BL = in_sizes[0] / D;        // B*L
    int L = 4096;
    if (BL % L != 0) L = BL;               // fallback for unexpected shapes
    const int B  = BL / L;
    const int D4 = D / 4;

    const int ngroups = (D4 + THREADS - 1) / THREADS;   // 2

    // one wave: 148 SMs x 4 resident blocks = 592 total
    int nstrips = 592 / (ngroups * B);
    if (nstrips < 1) nstrips = 1;
    if (nstrips > L) nstrips = L;

    dim3 grid(nstrips, ngroups, B);
    dwconv_kernel<<<grid, THREADS>>>(
        (const float4*)x, (const float4*)w, (const float4*)bi,
        (float4*)y, L, D4, nstrips);
}

// round 4
// speedup vs baseline: 1.0263x; 1.0263x over previous
#include <cuda_runtime.h>

// Depthwise causal conv1d, channel-last. x:(B,L,D) fp32; w:(K=4,1,D); b:(D,).
// y[b,l,d] = bias[d] + sum_k x[b,l+k-3,d]*w[k,d]
//
// R4: balanced strips (592 blocks = 148 SM x 4 resident, halo 3/55 = 5.4%)
// + deep front-batched loads (8 LDG.128 issued before any FMA/store -> MLP_p1=8),
// which is what made the R1 full-unroll kernel hit 75% DRAM.

#define THREADS 256
#define UNROLL 8

__global__ void __launch_bounds__(THREADS, 4) dwconv_kernel(
    const float4* __restrict__ x,
    const float4* __restrict__ w,
    const float4* __restrict__ bias,
    float4* __restrict__ y,
    int L, int D4, int nstrips)
{
    const int d4 = blockIdx.y * THREADS + threadIdx.x;  // channel group (fixed)
    const int b  = blockIdx.z;
    const int s  = blockIdx.x;

    // balanced partition of [0, L)
    const int l_start = (int)(((long)s * L) / nstrips);
    const int l_end   = (int)(((long)(s + 1) * L) / nstrips);

    const float4 w0 = w[0 * D4 + d4];
    const float4 w1 = w[1 * D4 + d4];
    const float4 w2 = w[2 * D4 + d4];
    const float4 w3 = w[3 * D4 + d4];
    const float4 bb = bias[d4];
    const float4 z4 = make_float4(0.f, 0.f, 0.f, 0.f);

    const int base = (b * L) * D4 + d4;   // fits 32-bit (max ~33.5M)

    // history x[l_start-3 .. l_start-1], zero-padded at sequence start
    float4 h0, h1, h2;
    if (l_start >= 3) {
        h0 = x[base + (l_start - 3) * D4];
        h1 = x[base + (l_start - 2) * D4];
        h2 = x[base + (l_start - 1) * D4];
    } else {
        h0 = z4; h1 = z4; h2 = z4;
    }

    for (int l = l_start; l < l_end; l += UNROLL) {
        // ---- batch all UNROLL loads up front (front-batched MLP) ----
        float4 xv[UNROLL];
        #pragma unroll
        for (int i = 0; i < UNROLL; ++i) {
            int ll = l + i;
            ll = (ll < l_end) ? ll : (l_end - 1);   // clamp: only final iter
            xv[i] = x[base + ll * D4];
        }

        // ---- compute (sliding history through the batch) ----
        float4 o[UNROLL];
        float4 a = h0, c = h1, e = h2;
        #pragma unroll
        for (int i = 0; i < UNROLL; ++i) {
            const float4 xc = xv[i];
            o[i].x = fmaf(w3.x, xc.x, fmaf(w2.x, e.x, fmaf(w1.x, c.x, fmaf(w0.x, a.x, bb.x))));
            o[i].y = fmaf(w3.y, xc.y, fmaf(w2.y, e.y, fmaf(w1.y, c.y, fmaf(w0.y, a.y, bb.y))));
            o[i].z = fmaf(w3.z, xc.z, fmaf(w2.z, e.z, fmaf(w1.z, c.z, fmaf(w0.z, a.z, bb.z))));
            o[i].w = fmaf(w3.w, xc.w, fmaf(w2.w, e.w, fmaf(w1.w, c.w, fmaf(w0.w, a.w, bb.w))));
            a = c; c = e; e = xc;
        }
        h0 = a; h1 = c; h2 = e;   // valid whenever another iteration follows

        // ---- predicated stores ----
        #pragma unroll
        for (int i = 0; i < UNROLL; ++i) {
            if (l + i < l_end) y[base + (l + i) * D4] = o[i];
        }
    }
}

extern "C" void kernel_launch(void* const* d_in, const int* in_sizes, int n_in,
                              void* d_out, int out_size)
{
    const float* x  = (const float*)d_in[0];
    const float* w  = (const float*)d_in[1];
    const float* bi = (const float*)d_in[2];
    float* y = (float*)d_out;

    const int D  = in_sizes[2];            // 2048
    const int BL = in_sizes[0] / D;        // B*L
    int L = 4096;
    if (BL % L != 0) L = BL;               // fallback for unexpected shapes
    const int B  = BL / L;
    const int D4 = D / 4;

    const int ngroups = (D4 + THREADS - 1) / THREADS;   // 2

    // exactly one resident wave: 148 SMs x 4 blocks = 592
    int nstrips = 592 / (ngroups * B);
    if (nstrips < 1) nstrips = 1;
    if (nstrips > L) nstrips = L;

    dim3 grid(nstrips, ngroups, B);
    dwconv_kernel<<<grid, THREADS>>>(
        (const float4*)x, (const float4*)w, (const float4*)bi,
        (float4*)y, L, D4, nstrips);
}